// round 1
// baseline (speedup 1.0000x reference)
#include <cuda_runtime.h>

#define MAXB 256
#define MAXC 1024
#define JT 8

// Scratch (static device globals — no allocation allowed)
__device__ float g_W[MAXB * MAXC];        // w[i,c] = m_counts[i,c]^2 as float
__device__ float g_modmax[MAXB * JT];
__device__ float g_idmin[MAXB * JT];

__device__ __forceinline__ float warpReduceSum(float v) {
#pragma unroll
    for (int o = 16; o > 0; o >>= 1)
        v += __shfl_xor_sync(0xffffffffu, v, o);
    return v;
}

// Block reduce: result valid on tid==0 only. sbuf must hold >= blockDim/32 floats.
__device__ __forceinline__ float blockReduceSum(float v, float* sbuf) {
    const int tid = threadIdx.x;
    v = warpReduceSum(v);
    if ((tid & 31) == 0) sbuf[tid >> 5] = v;
    __syncthreads();
    float r = 0.f;
    if (tid == 0) {
        const int nw = (blockDim.x + 31) >> 5;
        for (int w = 0; w < nw; ++w) r += sbuf[w];
    }
    __syncthreads();
    return r;
}

// ---------------------------------------------------------------------------
// Phase 1: per-row neighbor selection + thresholds + w[i,c] = m_counts^2
// One block per row i.
// ---------------------------------------------------------------------------
__global__ void phase1_kernel(const float* __restrict__ x,
                              const int* __restrict__ targets,
                              const int* __restrict__ subs,
                              const int* __restrict__ mcp,
                              int B, int C) {
    const int i = blockIdx.x;
    const int tid = threadIdx.x;
    __shared__ int s_nb[16];
    __shared__ float s_thr[16];
    __shared__ int s_mc;
    __shared__ float s_red[8];

    if (tid == 0) {
        int mc = mcp[0];
        if (mc > 16) mc = 16;
        if (mc < 0) mc = 0;
        const int ti = targets[i], si = subs[i];
        int cnt = 0;
        // stable argsort of (combined?0:1): combined cols ascending first
        for (int j = 0; j < B && cnt < mc; ++j)
            if (targets[j] == ti && subs[j] == si) s_nb[cnt++] = j;
        for (int j = 0; j < B && cnt < mc; ++j)
            if (!(targets[j] == ti && subs[j] == si)) s_nb[cnt++] = j;
        s_mc = cnt;
    }
    __syncthreads();
    const int mc = s_mc;
    const float* xi = x + (size_t)i * C;

    for (int k = 0; k < mc; ++k) {
        const float* xn = x + (size_t)s_nb[k] * C;
        float s = 0.f;
        for (int c = tid; c < C; c += blockDim.x)
            s += fabsf(xi[c] - xn[c]);
        s = blockReduceSum(s, s_red);
        if (tid == 0) s_thr[k] = (s / (float)C) * 0.5f;
        __syncthreads();
    }

    for (int c = tid; c < C; c += blockDim.x) {
        const float xic = xi[c];
        int cnt = 0;
        for (int k = 0; k < mc; ++k)
            cnt += (fabsf(xic - x[(size_t)s_nb[k] * C + c]) < s_thr[k]) ? 1 : 0;
        g_W[(size_t)i * C + c] = (float)(cnt * cnt);
    }
}

// ---------------------------------------------------------------------------
// Phase 2 (fast path, C == 1024): warp per row i, 32 j's per warp.
// grid = (JT, ceil(B/8)), block = 256 (8 warps).
// ---------------------------------------------------------------------------
__global__ __launch_bounds__(256) void phase2_kernel(
    const float* __restrict__ x,
    const int* __restrict__ targets,
    int B, int jtile) {
    const int lane = threadIdx.x & 31;
    const int warp = threadIdx.x >> 5;
    const int i = blockIdx.y * 8 + warp;
    const int jt = blockIdx.x;
    if (i >= B) return;

    const int ti = __ldg(&targets[i]);
    const float4* __restrict__ xrow = reinterpret_cast<const float4*>(x) + (size_t)i * 256;
    const float4* __restrict__ wrow = reinterpret_cast<const float4*>(g_W) + (size_t)i * 256;

    float4 xi[8], wi[8];
#pragma unroll
    for (int k = 0; k < 8; ++k) {
        xi[k] = __ldg(&xrow[lane + 32 * k]);
        wi[k] = __ldg(&wrow[lane + 32 * k]);
    }

    float modmax = 0.f;
    float idmin = __int_as_float(0x7f800000);  // +inf

    const int j0 = jt * jtile;
    const int j1 = (j0 + jtile < B) ? (j0 + jtile) : B;

    for (int j = j0; j < j1; ++j) {
        const float4* __restrict__ xjr = reinterpret_cast<const float4*>(x) + (size_t)j * 256;
        float4 d[8];
        float sabs = 0.f;
#pragma unroll
        for (int k = 0; k < 8; ++k) {
            const float4 xj = __ldg(&xjr[lane + 32 * k]);
            d[k].x = xi[k].x - xj.x;
            d[k].y = xi[k].y - xj.y;
            d[k].z = xi[k].z - xj.z;
            d[k].w = xi[k].w - xj.w;
            sabs += fabsf(d[k].x) + fabsf(d[k].y) + fabsf(d[k].z) + fabsf(d[k].w);
        }
        sabs = warpReduceSum(sabs);
        const float thr = sabs * (0.5f / 1024.f);

        const float4* __restrict__ wjr = reinterpret_cast<const float4*>(g_W) + (size_t)j * 256;
        float idsum = 0.f, modsum = 0.f;
#pragma unroll
        for (int k = 0; k < 8; ++k) {
            const float4 wj = __ldg(&wjr[lane + 32 * k]);
            float dd, d2;
            dd = d[k].x; d2 = dd * dd;
            if (fabsf(dd) < thr) idsum += d2;
            modsum += d2 * wi[k].x * wj.x;
            dd = d[k].y; d2 = dd * dd;
            if (fabsf(dd) < thr) idsum += d2;
            modsum += d2 * wi[k].y * wj.y;
            dd = d[k].z; d2 = dd * dd;
            if (fabsf(dd) < thr) idsum += d2;
            modsum += d2 * wi[k].z * wj.z;
            dd = d[k].w; d2 = dd * dd;
            if (fabsf(dd) < thr) idsum += d2;
            modsum += d2 * wi[k].w * wj.w;
        }
        idsum = warpReduceSum(idsum);
        modsum = warpReduceSum(modsum);

        const float modd = sqrtf(fmaxf(modsum, 1e-12f));
        modmax = fmaxf(modmax, modd);
        if (__ldg(&targets[j]) != ti) {
            const float idd = sqrtf(fmaxf(idsum, 1e-12f));
            idmin = fminf(idmin, idd);
        }
    }

    if (lane == 0) {
        g_modmax[i * JT + jt] = modmax;
        g_idmin[i * JT + jt] = idmin;
    }
}

// ---------------------------------------------------------------------------
// Phase 2 generic fallback (any C): one block per (i, j-tile).
// ---------------------------------------------------------------------------
__global__ void phase2_generic(const float* __restrict__ x,
                               const int* __restrict__ targets,
                               int B, int C, int jtile) {
    const int i = blockIdx.y;
    const int jt = blockIdx.x;
    const int tid = threadIdx.x;
    __shared__ float s_red[8];
    __shared__ float s_thr;

    const float* xi = x + (size_t)i * C;
    const float* wi = g_W + (size_t)i * C;
    const int ti = targets[i];
    float modmax = 0.f;
    float idmin = __int_as_float(0x7f800000);

    const int j0 = jt * jtile;
    const int j1 = (j0 + jtile < B) ? (j0 + jtile) : B;

    for (int j = j0; j < j1; ++j) {
        const float* xj = x + (size_t)j * C;
        const float* wj = g_W + (size_t)j * C;
        float sabs = 0.f;
        for (int c = tid; c < C; c += blockDim.x)
            sabs += fabsf(xi[c] - xj[c]);
        sabs = blockReduceSum(sabs, s_red);
        if (tid == 0) s_thr = (sabs / (float)C) * 0.5f;
        __syncthreads();
        const float thr = s_thr;

        float idsum = 0.f, modsum = 0.f;
        for (int c = tid; c < C; c += blockDim.x) {
            const float dd = xi[c] - xj[c];
            const float d2 = dd * dd;
            if (fabsf(dd) < thr) idsum += d2;
            modsum += d2 * wi[c] * wj[c];
        }
        idsum = blockReduceSum(idsum, s_red);
        modsum = blockReduceSum(modsum, s_red);
        if (tid == 0) {
            const float modd = sqrtf(fmaxf(modsum, 1e-12f));
            modmax = fmaxf(modmax, modd);
            if (targets[j] != ti) {
                const float idd = sqrtf(fmaxf(idsum, 1e-12f));
                idmin = fminf(idmin, idd);
            }
        }
        __syncthreads();
    }
    if (tid == 0) {
        g_modmax[i * JT + jt] = modmax;
        g_idmin[i * JT + jt] = idmin;
    }
}

// ---------------------------------------------------------------------------
// Finalize: per-row max/min across JT partials, hinge, mean.
// ---------------------------------------------------------------------------
__global__ void finalize_kernel(float* __restrict__ out, int B) {
    const int tid = threadIdx.x;
    __shared__ float s_red[8];
    float pr = 0.f;
    for (int i = tid; i < B; i += blockDim.x) {
        float mm = 0.f;
        float im = __int_as_float(0x7f800000);
#pragma unroll
        for (int k = 0; k < JT; ++k) {
            mm = fmaxf(mm, g_modmax[i * JT + k]);
            im = fminf(im, g_idmin[i * JT + k]);
        }
        const float v = mm * 10.f - im;   // -inf if im == inf -> hinged to 0
        pr += fmaxf(v, 0.f);
    }
    pr = blockReduceSum(pr, s_red);
    if (tid == 0) out[0] = pr / (float)B;
}

// ---------------------------------------------------------------------------
extern "C" void kernel_launch(void* const* d_in, const int* in_sizes, int n_in,
                              void* d_out, int out_size) {
    const float* x = (const float*)d_in[0];
    const int* targets = (const int*)d_in[1];
    const int* subs = (const int*)d_in[2];
    const int* mcp = (const int*)d_in[3];

    const int B = in_sizes[1];             // rows (256)
    const int C = in_sizes[0] / B;         // channels (1024)

    phase1_kernel<<<B, 256>>>(x, targets, subs, mcp, B, C);

    const int jtile = (B + JT - 1) / JT;
    if (C == 1024) {
        dim3 grid(JT, (B + 7) / 8);
        phase2_kernel<<<grid, 256>>>(x, targets, B, jtile);
    } else {
        dim3 grid(JT, B);
        phase2_generic<<<grid, 128>>>(x, targets, B, C, jtile);
    }

    finalize_kernel<<<1, 256>>>((float*)d_out, B);
}

// round 2
// speedup vs baseline: 1.5694x; 1.5694x over previous
#include <cuda_runtime.h>

#define MAXB 256
#define MAXC 1024

// Scratch (static device globals — no allocation allowed)
__device__ float g_W[MAXB * MAXC];   // w[i,c] = m_counts[i,c]^2 as float
__device__ int   g_modmax_i[MAXB];   // int-encoded non-negative float, atomicMax
__device__ int   g_idmin_i[MAXB];    // int-encoded non-negative float, atomicMin

__device__ __forceinline__ float warpReduceSum(float v) {
#pragma unroll
    for (int o = 16; o > 0; o >>= 1)
        v += __shfl_xor_sync(0xffffffffu, v, o);
    return v;
}

__device__ __forceinline__ float blockReduceSum(float v, float* sbuf) {
    const int tid = threadIdx.x;
    v = warpReduceSum(v);
    if ((tid & 31) == 0) sbuf[tid >> 5] = v;
    __syncthreads();
    float r = 0.f;
    if (tid == 0) {
        const int nw = (blockDim.x + 31) >> 5;
        for (int w = 0; w < nw; ++w) r += sbuf[w];
    }
    __syncthreads();
    return r;
}

// ---------------------------------------------------------------------------
// Phase 1: per-row neighbor selection + thresholds + w[i,c] = m_counts^2.
// One block (256 thr) per row i. Also clears the atomic result slots.
// ---------------------------------------------------------------------------
__global__ __launch_bounds__(256) void phase1_kernel(
    const float* __restrict__ x,
    const int* __restrict__ targets,
    const int* __restrict__ subs,
    const int* __restrict__ mcp,
    int B, int C) {
    const int i = blockIdx.x;
    const int tid = threadIdx.x;
    const int lane = tid & 31;
    const int warp = tid >> 5;

    __shared__ int s_t[MAXB];
    __shared__ int s_s[MAXB];
    __shared__ int s_nb[16];
    __shared__ float s_thr[16];
    __shared__ int s_mc;

    for (int j = tid; j < B; j += blockDim.x) {
        s_t[j] = targets[j];
        s_s[j] = subs[j];
    }
    if (tid == 0) {
        g_modmax_i[i] = 0;                 // max over non-negative floats
        g_idmin_i[i] = 0x7f800000;         // +inf
    }
    __syncthreads();

    if (tid == 0) {
        int mc = mcp[0];
        if (mc > 16) mc = 16;
        if (mc < 0) mc = 0;
        const int ti = s_t[i], si = s_s[i];
        int cnt = 0;
        // stable argsort of (combined?0:1): combined cols ascending first
        for (int j = 0; j < B && cnt < mc; ++j)
            if (s_t[j] == ti && s_s[j] == si) s_nb[cnt++] = j;
        for (int j = 0; j < B && cnt < mc; ++j)
            if (!(s_t[j] == ti && s_s[j] == si)) s_nb[cnt++] = j;
        s_mc = cnt;
    }
    __syncthreads();

    const int mc = s_mc;
    const float* __restrict__ xi = x + (size_t)i * C;

    // Thresholds: warp k handles neighbor k (mc <= 8 handled by 8 warps; loop
    // for the >8 general case).
    for (int k = warp; k < mc; k += (blockDim.x >> 5)) {
        const float* __restrict__ xn = x + (size_t)s_nb[k] * C;
        float s = 0.f;
        for (int c = lane; c < C; c += 32)
            s += fabsf(xi[c] - xn[c]);
        s = warpReduceSum(s);
        if (lane == 0) s_thr[k] = (s / (float)C) * 0.5f;
    }
    __syncthreads();

    // W[i,c] = cnt^2
    for (int c = tid; c < C; c += blockDim.x) {
        const float xic = xi[c];
        int cnt = 0;
        for (int k = 0; k < mc; ++k)
            cnt += (fabsf(xic - x[(size_t)s_nb[k] * C + c]) < s_thr[k]) ? 1 : 0;
        g_W[(size_t)i * C + c] = (float)(cnt * cnt);
    }
}

// ---------------------------------------------------------------------------
// Phase 2 fast path (C == 1024, B % 32 == 0): symmetric upper-triangle tiles.
// grid.x = nt*(nt+1)/2 tile pairs (nt = B/32), grid.y = 8 (rowgroup*2 + jhalf).
// Block = 256 (8 warps); warp w handles row i = tu*32 + rowgroup*8 + w,
// looping 16 columns j in tile tv. Results scattered to rows i AND j via
// int-encoded float RED.MAX / RED.MIN.
// ---------------------------------------------------------------------------
__global__ __launch_bounds__(256) void phase2_sym(
    const float* __restrict__ x,
    const int* __restrict__ targets,
    int B) {
    const int lane = threadIdx.x & 31;
    const int warp = threadIdx.x >> 5;
    const int nt = B >> 5;

    // map blockIdx.x -> (tu, tv), tu <= tv, row-major upper triangle
    int t = blockIdx.x;
    int tu = 0;
    while (t >= nt - tu) { t -= (nt - tu); ++tu; }
    const int tv = tu + t;

    const int rowgroup = blockIdx.y >> 1;
    const int jhalf = blockIdx.y & 1;
    const int i = tu * 32 + rowgroup * 8 + warp;
    const int jbase = tv * 32 + jhalf * 16;
    const bool crossTile = (tu != tv);

    const int ti = __ldg(&targets[i]);
    const float4* __restrict__ xrow = reinterpret_cast<const float4*>(x) + (size_t)i * 256;
    const float4* __restrict__ wrow = reinterpret_cast<const float4*>(g_W) + (size_t)i * 256;

    float4 xi[8], wi[8];
#pragma unroll
    for (int k = 0; k < 8; ++k) {
        xi[k] = __ldg(&xrow[lane + 32 * k]);
        wi[k] = __ldg(&wrow[lane + 32 * k]);
    }

    float modmax = 0.f;
    float idmin = __int_as_float(0x7f800000);

#pragma unroll 1
    for (int jj = 0; jj < 16; ++jj) {
        const int j = jbase + jj;
        const float4* __restrict__ xjr = reinterpret_cast<const float4*>(x) + (size_t)j * 256;
        float4 d[8];
        float sabs = 0.f;
#pragma unroll
        for (int k = 0; k < 8; ++k) {
            const float4 xj = __ldg(&xjr[lane + 32 * k]);
            d[k].x = xi[k].x - xj.x;
            d[k].y = xi[k].y - xj.y;
            d[k].z = xi[k].z - xj.z;
            d[k].w = xi[k].w - xj.w;
            sabs += fabsf(d[k].x) + fabsf(d[k].y) + fabsf(d[k].z) + fabsf(d[k].w);
        }
        sabs = warpReduceSum(sabs);
        const float thr = sabs * (0.5f / 1024.f);

        const float4* __restrict__ wjr = reinterpret_cast<const float4*>(g_W) + (size_t)j * 256;
        float idsum = 0.f, modsum = 0.f;
#pragma unroll
        for (int k = 0; k < 8; ++k) {
            const float4 wj = __ldg(&wjr[lane + 32 * k]);
            float dd, d2;
            dd = d[k].x; d2 = dd * dd;
            idsum += (fabsf(dd) < thr) ? d2 : 0.f;
            modsum = fmaf(d2 * wi[k].x, wj.x, modsum);
            dd = d[k].y; d2 = dd * dd;
            idsum += (fabsf(dd) < thr) ? d2 : 0.f;
            modsum = fmaf(d2 * wi[k].y, wj.y, modsum);
            dd = d[k].z; d2 = dd * dd;
            idsum += (fabsf(dd) < thr) ? d2 : 0.f;
            modsum = fmaf(d2 * wi[k].z, wj.z, modsum);
            dd = d[k].w; d2 = dd * dd;
            idsum += (fabsf(dd) < thr) ? d2 : 0.f;
            modsum = fmaf(d2 * wi[k].w, wj.w, modsum);
        }
        idsum = warpReduceSum(idsum);
        modsum = warpReduceSum(modsum);

        const float modd = sqrtf(fmaxf(modsum, 1e-12f));
        const float idd = sqrtf(fmaxf(idsum, 1e-12f));
        const int tj = __ldg(&targets[j]);
        const bool diffT = (tj != ti);

        modmax = fmaxf(modmax, modd);
        if (diffT) idmin = fminf(idmin, idd);

        if (lane == 0 && crossTile) {
            atomicMax(&g_modmax_i[j], __float_as_int(modd));
            if (diffT) atomicMin(&g_idmin_i[j], __float_as_int(idd));
        }
    }

    if (lane == 0) {
        atomicMax(&g_modmax_i[i], __float_as_int(modmax));
        atomicMin(&g_idmin_i[i], __float_as_int(idmin));
    }
}

// ---------------------------------------------------------------------------
// Phase 2 generic fallback (any C/B): block per (i, j-tile), atomics at end.
// ---------------------------------------------------------------------------
__global__ void phase2_generic(const float* __restrict__ x,
                               const int* __restrict__ targets,
                               int B, int C, int jtile) {
    const int i = blockIdx.y;
    const int jt = blockIdx.x;
    const int tid = threadIdx.x;
    __shared__ float s_red[8];
    __shared__ float s_thr;

    const float* xi = x + (size_t)i * C;
    const float* wi = g_W + (size_t)i * C;
    const int ti = targets[i];
    float modmax = 0.f;
    float idmin = __int_as_float(0x7f800000);

    const int j0 = jt * jtile;
    const int j1 = (j0 + jtile < B) ? (j0 + jtile) : B;

    for (int j = j0; j < j1; ++j) {
        const float* xj = x + (size_t)j * C;
        const float* wj = g_W + (size_t)j * C;
        float sabs = 0.f;
        for (int c = tid; c < C; c += blockDim.x)
            sabs += fabsf(xi[c] - xj[c]);
        sabs = blockReduceSum(sabs, s_red);
        if (tid == 0) s_thr = (sabs / (float)C) * 0.5f;
        __syncthreads();
        const float thr = s_thr;

        float idsum = 0.f, modsum = 0.f;
        for (int c = tid; c < C; c += blockDim.x) {
            const float dd = xi[c] - xj[c];
            const float d2 = dd * dd;
            if (fabsf(dd) < thr) idsum += d2;
            modsum += d2 * wi[c] * wj[c];
        }
        idsum = blockReduceSum(idsum, s_red);
        modsum = blockReduceSum(modsum, s_red);
        if (tid == 0) {
            const float modd = sqrtf(fmaxf(modsum, 1e-12f));
            modmax = fmaxf(modmax, modd);
            if (targets[j] != ti) {
                const float idd = sqrtf(fmaxf(idsum, 1e-12f));
                idmin = fminf(idmin, idd);
            }
        }
        __syncthreads();
    }
    if (tid == 0) {
        atomicMax(&g_modmax_i[i], __float_as_int(modmax));
        atomicMin(&g_idmin_i[i], __float_as_int(idmin));
    }
}

// ---------------------------------------------------------------------------
// Finalize: hinge + mean.
// ---------------------------------------------------------------------------
__global__ void finalize_kernel(float* __restrict__ out, int B) {
    const int tid = threadIdx.x;
    __shared__ float s_red[8];
    float pr = 0.f;
    for (int i = tid; i < B; i += blockDim.x) {
        const float mm = __int_as_float(g_modmax_i[i]);
        const float im = __int_as_float(g_idmin_i[i]);
        pr += fmaxf(mm * 10.f - im, 0.f);   // im=+inf -> -inf -> 0
    }
    pr = blockReduceSum(pr, s_red);
    if (tid == 0) out[0] = pr / (float)B;
}

// ---------------------------------------------------------------------------
extern "C" void kernel_launch(void* const* d_in, const int* in_sizes, int n_in,
                              void* d_out, int out_size) {
    const float* x = (const float*)d_in[0];
    const int* targets = (const int*)d_in[1];
    const int* subs = (const int*)d_in[2];
    const int* mcp = (const int*)d_in[3];

    const int B = in_sizes[1];             // rows (256)
    const int C = in_sizes[0] / B;         // channels (1024)

    phase1_kernel<<<B, 256>>>(x, targets, subs, mcp, B, C);

    if (C == 1024 && (B & 31) == 0 && B <= MAXB) {
        const int nt = B >> 5;
        dim3 grid(nt * (nt + 1) / 2, 8);
        phase2_sym<<<grid, 256>>>(x, targets, B);
    } else {
        const int JT = 8;
        const int jtile = (B + JT - 1) / JT;
        dim3 grid(JT, B);
        phase2_generic<<<grid, 128>>>(x, targets, B, C, jtile);
    }

    finalize_kernel<<<1, 256>>>((float*)d_out, B);
}

// round 3
// speedup vs baseline: 2.6516x; 1.6896x over previous
#include <cuda_runtime.h>

#define MAXB 256
#define MAXC 1024

// Scratch (static device globals — no allocation allowed)
__device__ float g_W[MAXB * MAXC];   // w[i,c] = m_counts[i,c]^2 as float
__device__ int   g_modmax_i[MAXB];   // int-encoded non-negative float, atomicMax
__device__ int   g_idmin_i[MAXB];    // int-encoded non-negative float, atomicMin

__device__ __forceinline__ float warpReduceSum(float v) {
#pragma unroll
    for (int o = 16; o > 0; o >>= 1)
        v += __shfl_xor_sync(0xffffffffu, v, o);
    return v;
}

__device__ __forceinline__ float blockReduceSum(float v, float* sbuf) {
    const int tid = threadIdx.x;
    v = warpReduceSum(v);
    if ((tid & 31) == 0) sbuf[tid >> 5] = v;
    __syncthreads();
    float r = 0.f;
    if (tid == 0) {
        const int nw = (blockDim.x + 31) >> 5;
        for (int w = 0; w < nw; ++w) r += sbuf[w];
    }
    __syncthreads();
    return r;
}

// ---------------------------------------------------------------------------
// Phase 1: per-row neighbor selection + thresholds + w[i,c] = m_counts^2.
// One block (256 thr) per row i. Neighbor selection via warp ballots (the
// previous serial tid==0 scan was a ~20k-cycle dependent chain = 24us).
// ---------------------------------------------------------------------------
__global__ __launch_bounds__(256) void phase1_kernel(
    const float* __restrict__ x,
    const int* __restrict__ targets,
    const int* __restrict__ subs,
    const int* __restrict__ mcp,
    int B, int C) {
    const int i = blockIdx.x;
    const int tid = threadIdx.x;
    const int lane = tid & 31;
    const int warp = tid >> 5;

    __shared__ int s_t[MAXB];
    __shared__ int s_s[MAXB];
    __shared__ unsigned s_match[8];
    __shared__ unsigned s_valid[8];
    __shared__ int s_nb[16];
    __shared__ float s_thr[16];
    __shared__ int s_mc;

    for (int j = tid; j < B; j += blockDim.x) {
        s_t[j] = targets[j];
        s_s[j] = subs[j];
    }
    if (tid == 0) {
        g_modmax_i[i] = 0;                 // max over non-negative floats
        g_idmin_i[i] = 0x7f800000;         // +inf
    }
    __syncthreads();

    // Ballot-based stable selection of the first mc "combined" columns
    // (same target & sub), then first non-combined as filler.
    {
        const int ti = s_t[i], si = s_s[i];
        const int j = tid;
        const bool valid = (j < B);
        const bool match = valid && (s_t[j] == ti) && (s_s[j] == si);
        const unsigned mm = __ballot_sync(0xffffffffu, match);
        const unsigned vv = __ballot_sync(0xffffffffu, valid);
        if (lane == 0) { s_match[warp] = mm; s_valid[warp] = vv; }
    }
    __syncthreads();

    if (tid == 0) {
        int mc = mcp[0];
        if (mc > 16) mc = 16;
        if (mc < 0) mc = 0;
        int cnt = 0;
        for (int w = 0; w < 8 && cnt < mc; ++w) {
            unsigned m = s_match[w];
            while (m && cnt < mc) {
                s_nb[cnt++] = w * 32 + (__ffs(m) - 1);
                m &= m - 1;
            }
        }
        for (int w = 0; w < 8 && cnt < mc; ++w) {
            unsigned m = s_valid[w] & ~s_match[w];
            while (m && cnt < mc) {
                s_nb[cnt++] = w * 32 + (__ffs(m) - 1);
                m &= m - 1;
            }
        }
        s_mc = cnt;
    }
    __syncthreads();

    const int mc = s_mc;
    const float* __restrict__ xi = x + (size_t)i * C;

    // Thresholds: warp k handles neighbor k.
    for (int k = warp; k < mc; k += (blockDim.x >> 5)) {
        const float* __restrict__ xn = x + (size_t)s_nb[k] * C;
        float s = 0.f;
        for (int c = lane; c < C; c += 32)
            s += fabsf(xi[c] - xn[c]);
        s = warpReduceSum(s);
        if (lane == 0) s_thr[k] = (s / (float)C) * 0.5f;
    }
    __syncthreads();

    // W[i,c] = cnt^2
    for (int c = tid; c < C; c += blockDim.x) {
        const float xic = xi[c];
        int cnt = 0;
        for (int k = 0; k < mc; ++k)
            cnt += (fabsf(xic - x[(size_t)s_nb[k] * C + c]) < s_thr[k]) ? 1 : 0;
        g_W[(size_t)i * C + c] = (float)(cnt * cnt);
    }
}

// ---------------------------------------------------------------------------
// Phase 2 fast path (C == 1024, B % 32 == 0): symmetric upper-triangle tiles.
// grid.x = nt*(nt+1)/2 tile pairs (nt = B/32), grid.y = 8 (rowgroup*2 + jhalf).
// Block = 256 (8 warps); warp w handles row i = tu*32 + rowgroup*8 + w.
// wi lives in SMEM (frees 32 regs -> higher occupancy); xi and d in regs.
// ---------------------------------------------------------------------------
__global__ __launch_bounds__(256) void phase2_sym(
    const float* __restrict__ x,
    const int* __restrict__ targets,
    int B) {
    const int lane = threadIdx.x & 31;
    const int warp = threadIdx.x >> 5;
    const int nt = B >> 5;

    __shared__ float4 s_wi[8][256];   // 32 KB: W row per warp

    // map blockIdx.x -> (tu, tv), tu <= tv, row-major upper triangle
    int t = blockIdx.x;
    int tu = 0;
    while (t >= nt - tu) { t -= (nt - tu); ++tu; }
    const int tv = tu + t;

    const int rowgroup = blockIdx.y >> 1;
    const int jhalf = blockIdx.y & 1;
    const int i = tu * 32 + rowgroup * 8 + warp;
    const int jbase = tv * 32 + jhalf * 16;
    const bool crossTile = (tu != tv);

    const int ti = __ldg(&targets[i]);
    const float4* __restrict__ xrow = reinterpret_cast<const float4*>(x) + (size_t)i * 256;
    const float4* __restrict__ wrow = reinterpret_cast<const float4*>(g_W) + (size_t)i * 256;

    float4 xi[8];
#pragma unroll
    for (int k = 0; k < 8; ++k) {
        xi[k] = __ldg(&xrow[lane + 32 * k]);
        s_wi[warp][lane + 32 * k] = __ldg(&wrow[lane + 32 * k]);
    }
    __syncwarp();  // s_wi[warp] used only by this warp

    float modmax = 0.f;
    float idmin = __int_as_float(0x7f800000);

#pragma unroll 1
    for (int jj = 0; jj < 16; ++jj) {
        const int j = jbase + jj;
        const float4* __restrict__ xjr = reinterpret_cast<const float4*>(x) + (size_t)j * 256;
        float4 d[8];
        float sabs = 0.f;
#pragma unroll
        for (int k = 0; k < 8; ++k) {
            const float4 xj = __ldg(&xjr[lane + 32 * k]);
            d[k].x = xi[k].x - xj.x;
            d[k].y = xi[k].y - xj.y;
            d[k].z = xi[k].z - xj.z;
            d[k].w = xi[k].w - xj.w;
            sabs += fabsf(d[k].x) + fabsf(d[k].y) + fabsf(d[k].z) + fabsf(d[k].w);
        }
        sabs = warpReduceSum(sabs);
        const float thr = sabs * (0.5f / 1024.f);

        const float4* __restrict__ wjr = reinterpret_cast<const float4*>(g_W) + (size_t)j * 256;
        float idsum = 0.f, modsum = 0.f;
#pragma unroll
        for (int k = 0; k < 8; ++k) {
            const float4 wj = __ldg(&wjr[lane + 32 * k]);
            const float4 wi = s_wi[warp][lane + 32 * k];
            float dd, d2;
            dd = d[k].x; d2 = dd * dd;
            idsum += (fabsf(dd) < thr) ? d2 : 0.f;
            modsum = fmaf(d2 * wi.x, wj.x, modsum);
            dd = d[k].y; d2 = dd * dd;
            idsum += (fabsf(dd) < thr) ? d2 : 0.f;
            modsum = fmaf(d2 * wi.y, wj.y, modsum);
            dd = d[k].z; d2 = dd * dd;
            idsum += (fabsf(dd) < thr) ? d2 : 0.f;
            modsum = fmaf(d2 * wi.z, wj.z, modsum);
            dd = d[k].w; d2 = dd * dd;
            idsum += (fabsf(dd) < thr) ? d2 : 0.f;
            modsum = fmaf(d2 * wi.w, wj.w, modsum);
        }
        idsum = warpReduceSum(idsum);
        modsum = warpReduceSum(modsum);

        const float modd = sqrtf(fmaxf(modsum, 1e-12f));
        const float idd = sqrtf(fmaxf(idsum, 1e-12f));
        const int tj = __ldg(&targets[j]);
        const bool diffT = (tj != ti);

        modmax = fmaxf(modmax, modd);
        if (diffT) idmin = fminf(idmin, idd);

        if (lane == 0 && crossTile) {
            atomicMax(&g_modmax_i[j], __float_as_int(modd));
            if (diffT) atomicMin(&g_idmin_i[j], __float_as_int(idd));
        }
    }

    if (lane == 0) {
        atomicMax(&g_modmax_i[i], __float_as_int(modmax));
        atomicMin(&g_idmin_i[i], __float_as_int(idmin));
    }
}

// ---------------------------------------------------------------------------
// Phase 2 generic fallback (any C/B): block per (i, j-tile), atomics at end.
// ---------------------------------------------------------------------------
__global__ void phase2_generic(const float* __restrict__ x,
                               const int* __restrict__ targets,
                               int B, int C, int jtile) {
    const int i = blockIdx.y;
    const int jt = blockIdx.x;
    const int tid = threadIdx.x;
    __shared__ float s_red[8];
    __shared__ float s_thr;

    const float* xi = x + (size_t)i * C;
    const float* wi = g_W + (size_t)i * C;
    const int ti = targets[i];
    float modmax = 0.f;
    float idmin = __int_as_float(0x7f800000);

    const int j0 = jt * jtile;
    const int j1 = (j0 + jtile < B) ? (j0 + jtile) : B;

    for (int j = j0; j < j1; ++j) {
        const float* xj = x + (size_t)j * C;
        const float* wj = g_W + (size_t)j * C;
        float sabs = 0.f;
        for (int c = tid; c < C; c += blockDim.x)
            sabs += fabsf(xi[c] - xj[c]);
        sabs = blockReduceSum(sabs, s_red);
        if (tid == 0) s_thr = (sabs / (float)C) * 0.5f;
        __syncthreads();
        const float thr = s_thr;

        float idsum = 0.f, modsum = 0.f;
        for (int c = tid; c < C; c += blockDim.x) {
            const float dd = xi[c] - xj[c];
            const float d2 = dd * dd;
            if (fabsf(dd) < thr) idsum += d2;
            modsum += d2 * wi[c] * wj[c];
        }
        idsum = blockReduceSum(idsum, s_red);
        modsum = blockReduceSum(modsum, s_red);
        if (tid == 0) {
            const float modd = sqrtf(fmaxf(modsum, 1e-12f));
            modmax = fmaxf(modmax, modd);
            if (targets[j] != ti) {
                const float idd = sqrtf(fmaxf(idsum, 1e-12f));
                idmin = fminf(idmin, idd);
            }
        }
        __syncthreads();
    }
    if (tid == 0) {
        atomicMax(&g_modmax_i[i], __float_as_int(modmax));
        atomicMin(&g_idmin_i[i], __float_as_int(idmin));
    }
}

// ---------------------------------------------------------------------------
// Finalize: hinge + mean.
// ---------------------------------------------------------------------------
__global__ void finalize_kernel(float* __restrict__ out, int B) {
    const int tid = threadIdx.x;
    __shared__ float s_red[8];
    float pr = 0.f;
    for (int i = tid; i < B; i += blockDim.x) {
        const float mm = __int_as_float(g_modmax_i[i]);
        const float im = __int_as_float(g_idmin_i[i]);
        pr += fmaxf(mm * 10.f - im, 0.f);   // im=+inf -> -inf -> 0
    }
    pr = blockReduceSum(pr, s_red);
    if (tid == 0) out[0] = pr / (float)B;
}

// ---------------------------------------------------------------------------
extern "C" void kernel_launch(void* const* d_in, const int* in_sizes, int n_in,
                              void* d_out, int out_size) {
    const float* x = (const float*)d_in[0];
    const int* targets = (const int*)d_in[1];
    const int* subs = (const int*)d_in[2];
    const int* mcp = (const int*)d_in[3];

    const int B = in_sizes[1];             // rows (256)
    const int C = in_sizes[0] / B;         // channels (1024)

    phase1_kernel<<<B, 256>>>(x, targets, subs, mcp, B, C);

    if (C == 1024 && (B & 31) == 0 && B <= MAXB) {
        const int nt = B >> 5;
        dim3 grid(nt * (nt + 1) / 2, 8);
        phase2_sym<<<grid, 256>>>(x, targets, B);
    } else {
        const int JT = 8;
        const int jtile = (B + JT - 1) / JT;
        dim3 grid(JT, B);
        phase2_generic<<<grid, 128>>>(x, targets, B, C, jtile);
    }

    finalize_kernel<<<1, 256>>>((float*)d_out, B);
}